// round 14
// baseline (speedup 1.0000x reference)
#include <cuda_runtime.h>
#include <cstdint>

#define RADIUS 1.0f
#define TPB 256
#define F4_PER_THREAD 3                      // 4 rows = 12 floats = 3 float4 per thread
#define TILE_F4 (TPB * F4_PER_THREAD)        // 768 float4 per array per block
#define TILE_BYTES (TILE_F4 * 16)            // 12288 bytes per array

__device__ __forceinline__ uint32_t smem_u32(const void* p) {
    return (uint32_t)__cvta_generic_to_shared(p);
}

__global__ __launch_bounds__(TPB)
void circle_proj_kernel(const float4* __restrict__ x,
                        const float4* __restrict__ c,
                        float4* __restrict__ out,
                        int n_f4)            // total float4 per array
{
    __shared__ __align__(16) float4 xs[TILE_F4];
    __shared__ __align__(16) float4 cs[TILE_F4];
    __shared__ __align__(8)  uint64_t mbar;

    const int tid  = threadIdx.x;
    const int base = blockIdx.x * TILE_F4;
    const bool full_tile = (base + TILE_F4 <= n_f4);

    // ---------------- Load phase: two 12KB TMA bulk copies ----------------
    if (full_tile) {
        if (tid == 0) {
            uint32_t mb = smem_u32(&mbar);
            asm volatile("mbarrier.init.shared.b64 [%0], 1;" :: "r"(mb) : "memory");
            asm volatile("fence.proxy.async.shared::cta;" ::: "memory");
            asm volatile("mbarrier.arrive.expect_tx.shared.b64 _, [%0], %1;"
                         :: "r"(mb), "r"((uint32_t)(2 * TILE_BYTES)) : "memory");
            asm volatile("cp.async.bulk.shared::cta.global.mbarrier::complete_tx::bytes "
                         "[%0], [%1], %2, [%3];"
                         :: "r"(smem_u32(xs)), "l"(x + base),
                            "r"((uint32_t)TILE_BYTES), "r"(mb) : "memory");
            asm volatile("cp.async.bulk.shared::cta.global.mbarrier::complete_tx::bytes "
                         "[%0], [%1], %2, [%3];"
                         :: "r"(smem_u32(cs)), "l"(c + base),
                            "r"((uint32_t)TILE_BYTES), "r"(mb) : "memory");
        }
        __syncthreads();   // mbarrier.init visible to all waiters
        {
            uint32_t mb = smem_u32(&mbar);
            asm volatile(
                "{\n\t"
                ".reg .pred P1;\n\t"
                "WAIT_LOOP_%=:\n\t"
                "mbarrier.try_wait.parity.acquire.cta.shared::cta.b64 P1, [%0], 0, 0x989680;\n\t"
                "@P1 bra.uni WAIT_DONE_%=;\n\t"
                "bra.uni WAIT_LOOP_%=;\n\t"
                "WAIT_DONE_%=:\n\t"
                "}"
                :: "r"(mb) : "memory");
        }
    } else {
        // Partial-tile fallback (never taken for B=8388608)
#pragma unroll
        for (int i = 0; i < F4_PER_THREAD; i++) {
            int idx = i * TPB + tid;
            if (base + idx < n_f4) {
                xs[idx] = x[base + idx];
                cs[idx] = c[base + idx];
            }
        }
        __syncthreads();
    }

    // ---------------- Compute phase ----------------
    // Thread-private 48B region of smem (conflict-free for LDS/STS.128:
    // 8-lane phases hit 8 distinct 16B slots spanning all 32 banks).
    if (full_tile || (base + (tid + 1) * 3 <= n_f4)) {
        float4 x0 = xs[tid * 3 + 0];
        float4 x1 = xs[tid * 3 + 1];
        float4 x2 = xs[tid * 3 + 2];
        float4 c0 = cs[tid * 3 + 0];
        float4 c1 = cs[tid * 3 + 1];
        float4 c2 = cs[tid * 3 + 2];

        float xv[12] = {x0.x, x0.y, x0.z, x0.w, x1.x, x1.y, x1.z, x1.w,
                        x2.x, x2.y, x2.z, x2.w};
        float cv[12] = {c0.x, c0.y, c0.z, c0.w, c1.x, c1.y, c1.z, c1.w,
                        c2.x, c2.y, c2.z, c2.w};
        float ov[12];

#pragma unroll
        for (int r = 0; r < 4; r++) {
            float dx = xv[3 * r + 0] - cv[3 * r + 0];
            float dy = xv[3 * r + 1] - cv[3 * r + 1];
            float dz = xv[3 * r + 2] - cv[3 * r + 2];
            float n2 = fmaf(dx, dx, fmaf(dy, dy, dz * dz));
            float s  = fminf(1.0f, RADIUS * rsqrtf(fmaxf(n2, 1e-24f)));
            ov[3 * r + 0] = fmaf(dx, s, cv[3 * r + 0]);
            ov[3 * r + 1] = fmaf(dy, s, cv[3 * r + 1]);
            ov[3 * r + 2] = fmaf(dz, s, cv[3 * r + 2]);
        }

        xs[tid * 3 + 0] = make_float4(ov[0], ov[1], ov[2],  ov[3]);
        xs[tid * 3 + 1] = make_float4(ov[4], ov[5], ov[6],  ov[7]);
        xs[tid * 3 + 2] = make_float4(ov[8], ov[9], ov[10], ov[11]);
    }
    __syncthreads();

    // ---------------- Store phase: one 12KB TMA bulk copy ----------------
    if (full_tile) {
        if (tid == 0) {
            asm volatile("fence.proxy.async.shared::cta;" ::: "memory");
            asm volatile("cp.async.bulk.global.shared::cta.bulk_group [%0], [%1], %2;"
                         :: "l"(out + base), "r"(smem_u32(xs)),
                            "r"((uint32_t)TILE_BYTES) : "memory");
            asm volatile("cp.async.bulk.commit_group;" ::: "memory");
            // .read: only wait until smem source is fully read (safe to free at
            // CTA exit); global writes drain in background, ordered before the
            // end-of-grid implicit sync. Cuts per-CTA exit latency.
            asm volatile("cp.async.bulk.wait_group.read 0;" ::: "memory");
        }
    } else {
#pragma unroll
        for (int i = 0; i < F4_PER_THREAD; i++) {
            int idx = i * TPB + tid;
            if (base + idx < n_f4)
                out[base + idx] = xs[idx];
        }
    }
}

extern "C" void kernel_launch(void* const* d_in, const int* in_sizes, int n_in,
                              void* d_out, int out_size)
{
    const float4* x = (const float4*)d_in[0];
    const float4* c = (const float4*)d_in[1];
    float4* out = (float4*)d_out;

    int n_f4 = in_sizes[0] / 4;                      // B*3/4 = 6,291,456
    int blocks = (n_f4 + TILE_F4 - 1) / TILE_F4;     // 8192 exact
    circle_proj_kernel<<<blocks, TPB>>>(x, c, out, n_f4);
}

// round 15
// speedup vs baseline: 1.0336x; 1.0336x over previous
#include <cuda_runtime.h>
#include <cstdint>

#define RADIUS 1.0f
#define TPB 256
#define F4_PER_THREAD 3                      // 4 rows = 12 floats = 3 float4 per thread
#define TILE_F4 (TPB * F4_PER_THREAD)        // 768 float4 per array per block
#define TILE_BYTES (TILE_F4 * 16)            // 12288 bytes per array

__device__ __forceinline__ uint32_t smem_u32(const void* p) {
    return (uint32_t)__cvta_generic_to_shared(p);
}

__global__ __launch_bounds__(TPB)
void circle_proj_kernel(const float4* __restrict__ x,
                        const float4* __restrict__ c,
                        float4* __restrict__ out,
                        int n_f4)            // total float4 per array
{
    __shared__ __align__(16) float4 xs[TILE_F4];
    __shared__ __align__(16) float4 cs[TILE_F4];
    __shared__ __align__(8)  uint64_t mbar;

    const int tid  = threadIdx.x;
    const int base = blockIdx.x * TILE_F4;
    const bool full_tile = (base + TILE_F4 <= n_f4);

    // ---------------- Load phase: two 12KB TMA bulk copies ----------------
    if (full_tile) {
        if (tid == 0) {
            uint32_t mb = smem_u32(&mbar);
            asm volatile("mbarrier.init.shared.b64 [%0], 1;" :: "r"(mb) : "memory");
            asm volatile("fence.proxy.async.shared::cta;" ::: "memory");
            asm volatile("mbarrier.arrive.expect_tx.shared.b64 _, [%0], %1;"
                         :: "r"(mb), "r"((uint32_t)(2 * TILE_BYTES)) : "memory");
            asm volatile("cp.async.bulk.shared::cta.global.mbarrier::complete_tx::bytes "
                         "[%0], [%1], %2, [%3];"
                         :: "r"(smem_u32(xs)), "l"(x + base),
                            "r"((uint32_t)TILE_BYTES), "r"(mb) : "memory");
            asm volatile("cp.async.bulk.shared::cta.global.mbarrier::complete_tx::bytes "
                         "[%0], [%1], %2, [%3];"
                         :: "r"(smem_u32(cs)), "l"(c + base),
                            "r"((uint32_t)TILE_BYTES), "r"(mb) : "memory");
        }
        __syncthreads();   // mbarrier.init visible to all waiters
        {
            uint32_t mb = smem_u32(&mbar);
            asm volatile(
                "{\n\t"
                ".reg .pred P1;\n\t"
                "WAIT_LOOP_%=:\n\t"
                "mbarrier.try_wait.parity.acquire.cta.shared::cta.b64 P1, [%0], 0, 0x989680;\n\t"
                "@P1 bra.uni WAIT_DONE_%=;\n\t"
                "bra.uni WAIT_LOOP_%=;\n\t"
                "WAIT_DONE_%=:\n\t"
                "}"
                :: "r"(mb) : "memory");
        }
    } else {
        // Partial-tile fallback (never taken for B=8388608)
#pragma unroll
        for (int i = 0; i < F4_PER_THREAD; i++) {
            int idx = i * TPB + tid;
            if (base + idx < n_f4) {
                xs[idx] = x[base + idx];
                cs[idx] = c[base + idx];
            }
        }
        __syncthreads();
    }

    // ---------------- Compute phase ----------------
    // Thread-private 48B region of smem (conflict-free for LDS/STS.128:
    // 8-lane phases hit 8 distinct 16B slots spanning all 32 banks).
    if (full_tile || (base + (tid + 1) * 3 <= n_f4)) {
        float4 x0 = xs[tid * 3 + 0];
        float4 x1 = xs[tid * 3 + 1];
        float4 x2 = xs[tid * 3 + 2];
        float4 c0 = cs[tid * 3 + 0];
        float4 c1 = cs[tid * 3 + 1];
        float4 c2 = cs[tid * 3 + 2];

        float xv[12] = {x0.x, x0.y, x0.z, x0.w, x1.x, x1.y, x1.z, x1.w,
                        x2.x, x2.y, x2.z, x2.w};
        float cv[12] = {c0.x, c0.y, c0.z, c0.w, c1.x, c1.y, c1.z, c1.w,
                        c2.x, c2.y, c2.z, c2.w};
        float ov[12];

#pragma unroll
        for (int r = 0; r < 4; r++) {
            float dx = xv[3 * r + 0] - cv[3 * r + 0];
            float dy = xv[3 * r + 1] - cv[3 * r + 1];
            float dz = xv[3 * r + 2] - cv[3 * r + 2];
            float n2 = fmaf(dx, dx, fmaf(dy, dy, dz * dz));
            float s  = fminf(1.0f, RADIUS * rsqrtf(fmaxf(n2, 1e-24f)));
            ov[3 * r + 0] = fmaf(dx, s, cv[3 * r + 0]);
            ov[3 * r + 1] = fmaf(dy, s, cv[3 * r + 1]);
            ov[3 * r + 2] = fmaf(dz, s, cv[3 * r + 2]);
        }

        xs[tid * 3 + 0] = make_float4(ov[0], ov[1], ov[2],  ov[3]);
        xs[tid * 3 + 1] = make_float4(ov[4], ov[5], ov[6],  ov[7]);
        xs[tid * 3 + 2] = make_float4(ov[8], ov[9], ov[10], ov[11]);
    }
    __syncthreads();

    // ---------------- Store phase: one 12KB TMA bulk copy ----------------
    if (full_tile) {
        if (tid == 0) {
            asm volatile("fence.proxy.async.shared::cta;" ::: "memory");
            asm volatile("cp.async.bulk.global.shared::cta.bulk_group [%0], [%1], %2;"
                         :: "l"(out + base), "r"(smem_u32(xs)),
                            "r"((uint32_t)TILE_BYTES) : "memory");
            asm volatile("cp.async.bulk.commit_group;" ::: "memory");
            asm volatile("cp.async.bulk.wait_group 0;" ::: "memory");
        }
    } else {
#pragma unroll
        for (int i = 0; i < F4_PER_THREAD; i++) {
            int idx = i * TPB + tid;
            if (base + idx < n_f4)
                out[base + idx] = xs[idx];
        }
    }
}

extern "C" void kernel_launch(void* const* d_in, const int* in_sizes, int n_in,
                              void* d_out, int out_size)
{
    const float4* x = (const float4*)d_in[0];
    const float4* c = (const float4*)d_in[1];
    float4* out = (float4*)d_out;

    int n_f4 = in_sizes[0] / 4;                      // B*3/4 = 6,291,456
    int blocks = (n_f4 + TILE_F4 - 1) / TILE_F4;     // 8192 exact
    circle_proj_kernel<<<blocks, TPB>>>(x, c, out, n_f4);
}